// round 16
// baseline (speedup 1.0000x reference)
#include <cuda_runtime.h>
#include <cuda_pipeline.h>
#include <cstdint>

#define F_IN   10000
#define F_PAD  10240     // padded to 80 groups of 128 columns
#define NROWS  4096
#define GROUPS 80        // column groups of 128
#define WARPS  4         // warps per block (one group each)
#define RB     32        // rows per block (smaller -> smoother wave tail)
#define CH     4         // rows per cp.async chunk (double-buffered)
#define NC     (RB / CH) // chunks per block (8, even)
#define NPART  (GROUPS * 8)          // 640 partials per row
#define L2E    1.4426950408889634f
#define LN2    0.6931471805599453f
#define HL2PI2 1.3257480647361593f   // 0.5*log2(2*pi)

// scratch (no allocations allowed)
__device__ float g_pp[F_PAD * 9];               // per-column [m][{-K, B, C_}] base-2 Horner params
__device__ float g_part[(size_t)NROWS * NPART]; // per-row partials, row-major

__device__ __forceinline__ float ex2(float x) {
    float r; asm("ex2.approx.ftz.f32 %0, %1;" : "=f"(r) : "f"(x)); return r;
}
__device__ __forceinline__ float lg2(float x) {
    float r; asm("lg2.approx.ftz.f32 %0, %1;" : "=f"(r) : "f"(x)); return r;
}
// Packed f32x2 helpers (Blackwell FFMA2). x from float4 LDS is already in
// aligned register pairs, so pack/unpack movs coalesce away in SASS.
__device__ __forceinline__ uint64_t pk2(float lo, float hi) {
    uint64_t r; asm("mov.b64 %0, {%1, %2};" : "=l"(r) : "f"(lo), "f"(hi)); return r;
}
__device__ __forceinline__ void upk2(float& lo, float& hi, uint64_t v) {
    asm("mov.b64 {%0, %1}, %2;" : "=f"(lo), "=f"(hi) : "l"(v));
}
__device__ __forceinline__ uint64_t fma2(uint64_t a, uint64_t b, uint64_t c) {
    uint64_t r; asm("fma.rn.f32x2 %0, %1, %2, %3;" : "=l"(r) : "l"(a), "l"(b), "l"(c)); return r;
}

// Empty kernels: keep the ncu capture window (-s 5 -c 1) on spn_main (4th launch).
__global__ void dummy_a_kernel() {}
__global__ void dummy_b_kernel() {}

// Kernel 1: one thread per (f, m). Folds w1 log-softmax, log(std), permutation
// into per-column base-2 Horner constants: t_m(x) = (-K x + B) x + C_.
// Pad columns contribute exactly 0: t0 = 0, t1 = t2 = -1e30 (garbage x is
// harmless there — enables unpredicated clamped loads in the main kernel).
__global__ void prep_kernel(const float* __restrict__ means,
                            const float* __restrict__ stds,
                            const float* __restrict__ w1,
                            const int*   __restrict__ idx) {
    int t = blockIdx.x * blockDim.x + threadIdx.x;
    int f = t / 3, m = t - f * 3;
    if (f >= F_PAD) return;
    if (f >= F_IN) {
        if (m == 0) {
            float* q = &g_pp[(size_t)f * 9];
            q[0]=0.f; q[1]=0.f; q[2]=0.f;
            q[3]=0.f; q[4]=0.f; q[5]=-1e30f;
            q[6]=0.f; q[7]=0.f; q[8]=-1e30f;
        }
        return;
    }
    float u0 = w1[f*3+0]*L2E, u1 = w1[f*3+1]*L2E, u2 = w1[f*3+2]*L2E;
    float mu = fmaxf(u0, fmaxf(u1, u2));
    float l2 = mu + lg2(ex2(u0-mu) + ex2(u1-mu) + ex2(u2-mu));  // log2 softmax denom
    float um   = (m == 0) ? u0 : (m == 1 ? u1 : u2);
    float mean = means[f*3+m];
    float sd   = stds[f*3+m];
    float K    = 0.7213475204444817f / (sd * sd);   // 0.5*log2(e)/sd^2
    float A    = (um - l2) - lg2(sd) - HL2PI2;
    float* q = &g_pp[(size_t)idx[f] * 9 + m * 3];
    q[0] = -K;
    q[1] = 2.0f * K * mean;
    q[2] = A - K * mean * mean;
}

// Kernel 2: R13 structure (warp = 128 cols, lane = 4 consecutive cols,
// double-buffered cp.async 4-row chunks, compile-time buffer selection,
// hoisted output pointer) with two changes:
//  - RB 64->32: grid 2560 halves the wave-quantization tail (1280 blocks vs
//    1184 concurrent left a ~96-block lone-wave tail in R13)
//  - Horner evaluated with packed fma.rn.f32x2: 6 FFMA2 per row instead of
//    12 FFMA, at identical register cost (params pre-packed once).
// Per row: (a = sum mx, p = prod(1+s)); 2-step butterfly, ONE lg2,
// lanes 0-7 store 8 partials.
__global__ __launch_bounds__(WARPS * 32, 8) void spn_main(const float* __restrict__ x) {
    const int lane = threadIdx.x & 31;
    const int w    = threadIdx.x >> 5;
    const int g    = blockIdx.x * WARPS + w;      // column group 0..79
    const int r0   = blockIdx.y * RB;
    const int cbase = g * 128 + lane * 4;         // 4 consecutive columns

    __shared__ float4 buf[WARPS][2][CH][32];      // per-warp double-buffered chunks

    // Load params scalar, pack per column-pair: [pair][m] for cols (0,1),(2,3).
    uint64_t nk2[2][3], pb2[2][3], pc2[2][3];
    #pragma unroll
    for (int j = 0; j < 2; j++) {
        const float* pa = &g_pp[(size_t)(cbase + 2*j) * 9];
        const float* pbp = &g_pp[(size_t)(cbase + 2*j + 1) * 9];
        #pragma unroll
        for (int m = 0; m < 3; m++) {
            nk2[j][m] = pk2(__ldg(pa + m*3 + 0), __ldg(pbp + m*3 + 0));
            pb2[j][m] = pk2(__ldg(pa + m*3 + 1), __ldg(pbp + m*3 + 1));
            pc2[j][m] = pk2(__ldg(pa + m*3 + 2), __ldg(pbp + m*3 + 2));
        }
    }
    // Clamp OOB lanes to a valid address; pad params zero their contribution.
    const int ccl = (cbase < F_IN) ? cbase : (F_IN - 4);
    const float* gp = x + (size_t)r0 * F_IN + ccl;

    float4* s0 = &buf[w][0][0][lane];   // row stride = 32 float4s, imm offsets
    float4* s1 = &buf[w][1][0][lane];

    float* outp = g_part + (size_t)r0 * NPART + g * 8 + lane;
    const bool wr = (lane < 8);

    auto body = [&](float4 xv4) {
        const uint64_t xp[2] = { pk2(xv4.x, xv4.y), pk2(xv4.z, xv4.w) };
        float a = 0.0f, p = 1.0f;
        #pragma unroll
        for (int j = 0; j < 2; j++) {
            uint64_t u0 = fma2(fma2(xp[j], nk2[j][0], pb2[j][0]), xp[j], pc2[j][0]);
            uint64_t u1 = fma2(fma2(xp[j], nk2[j][1], pb2[j][1]), xp[j], pc2[j][1]);
            uint64_t u2 = fma2(fma2(xp[j], nk2[j][2], pb2[j][2]), xp[j], pc2[j][2]);
            float t0a, t0b, t1a, t1b, t2a, t2b;
            upk2(t0a, t0b, u0);
            upk2(t1a, t1b, u1);
            upk2(t2a, t2b, u2);
            {   // column 2j
                float hi = fmaxf(t0a, t1a), lo = fminf(t0a, t1a);
                float mx = fmaxf(hi, t2a), md = fminf(hi, t2a);
                float s  = ex2(md - mx) + ex2(lo - mx);
                a += mx;
                p = fmaf(s, p, p);
            }
            {   // column 2j+1
                float hi = fmaxf(t0b, t1b), lo = fminf(t0b, t1b);
                float mx = fmaxf(hi, t2b), md = fminf(hi, t2b);
                float s  = ex2(md - mx) + ex2(lo - mx);
                a += mx;
                p = fmaf(s, p, p);
            }
        }
        a += __shfl_xor_sync(0xffffffffu, a, 16);
        p *= __shfl_xor_sync(0xffffffffu, p, 16);
        a += __shfl_xor_sync(0xffffffffu, a, 8);
        p *= __shfl_xor_sync(0xffffffffu, p, 8);
        float v = a + lg2(p);      // product of 4 lanes <= 3^16, no overflow
        if (wr) *outp = v;
        outp += NPART;
    };

    // Prologue: chunk 0 -> buffer 0.
    #pragma unroll
    for (int i = 0; i < CH; i++)
        __pipeline_memcpy_async(s0 + i * 32, gp + (size_t)i * F_IN, 16);
    __pipeline_commit();
    gp += (size_t)CH * F_IN;

    #pragma unroll 1
    for (int k = 0; k < NC; k += 2) {
        // Issue chunk k+1 -> buffer 1 (always exists: NC even).
        #pragma unroll
        for (int i = 0; i < CH; i++)
            __pipeline_memcpy_async(s1 + i * 32, gp + (size_t)i * F_IN, 16);
        gp += (size_t)CH * F_IN;
        __pipeline_commit();
        __pipeline_wait_prior(1);       // chunk k ready in buffer 0
        #pragma unroll
        for (int i = 0; i < CH; i++) body(s0[i * 32]);

        // Issue chunk k+2 -> buffer 0 (if it exists).
        if (k + 2 < NC) {
            #pragma unroll
            for (int i = 0; i < CH; i++)
                __pipeline_memcpy_async(s0 + i * 32, gp + (size_t)i * F_IN, 16);
            gp += (size_t)CH * F_IN;
        }
        __pipeline_commit();            // (possibly empty group keeps counts aligned)
        __pipeline_wait_prior(1);       // chunk k+1 ready in buffer 1
        #pragma unroll
        for (int i = 0; i < CH; i++) body(s1[i * 32]);
    }
}

// Kernel 3: fold 640 partials per row (one warp per row, float4 loads).
__global__ void reduce_kernel(float* __restrict__ out) {
    const int lane = threadIdx.x & 31;
    const int n    = blockIdx.x * (blockDim.x >> 5) + (threadIdx.x >> 5);
    if (n >= NROWS) return;
    const float4* p4 = (const float4*)&g_part[(size_t)n * NPART];  // 160 float4s
    float s = 0.0f;
    #pragma unroll
    for (int i = 0; i < NPART / 128; i++) {   // 5 iterations
        float4 v = p4[lane + i * 32];
        s += (v.x + v.y) + (v.z + v.w);
    }
    #pragma unroll
    for (int off = 16; off; off >>= 1)
        s += __shfl_xor_sync(0xffffffffu, s, off);
    if (lane == 0) out[n] = s * LN2;
}

extern "C" void kernel_launch(void* const* d_in, const int* in_sizes, int n_in,
                              void* d_out, int out_size) {
    const float* x     = (const float*)d_in[0];
    const float* means = (const float*)d_in[1];
    const float* stds  = (const float*)d_in[2];
    const float* w1    = (const float*)d_in[3];
    // d_in[4..7] = w2..w5: provably no-ops (log_softmax over size-1 axis == 0)
    const int*   idx   = (const int*)d_in[8];

    prep_kernel<<<(F_PAD * 3 + 127) / 128, 128>>>(means, stds, w1, idx);
    dummy_a_kernel<<<1, 32>>>();   // ncu -s 5 alignment: spn_main at slot 6
    dummy_b_kernel<<<1, 32>>>();
    spn_main<<<dim3(GROUPS / WARPS, NROWS / RB), WARPS * 32>>>(x);
    reduce_kernel<<<NROWS / 8, 256>>>((float*)d_out);
}